// round 7
// baseline (speedup 1.0000x reference)
#include <cuda_runtime.h>
#include <math.h>

#define NB 4
#define CC 64
#define HH 64
#define WW 64
#define LL 4096
#define FF 256

#define OUT_S 0
#define OUT_U 16384
#define OUT_R 32768
#define OUT_A 9469952

typedef unsigned long long ull;

__device__ float g_Ut[NB][FF][LL];     // normalized masked features, k-major
__device__ float g_P[NB][HH][WW];
__device__ float g_rnorm[NB][LL];
__device__ int   g_arg[NB][LL];
__device__ ull   g_best[NB][LL];       // packed (sortable(v)<<32) | ~l

__device__ __constant__ int c_dy[4] = {-1, -1, -1, 0};
__device__ __constant__ int c_dx[4] = {-1,  0,  1, -1};

// packed-f32x2 FMA: two fp32 FMAs per instruction, bit-identical per lane
#define FMA2(d, a, b) asm("fma.rn.f32x2 %0, %1, %2, %0;" : "+l"(d) : "l"(a), "l"(b))
#define DUP2(d, f)    asm("mov.b64 %0, {%1, %1};" : "=l"(d) : "r"(__float_as_uint(f)))

#define CP16(dst, src) asm volatile( \
    "cp.async.cg.shared.global [%0], [%1], 16;" :: "r"(dst), "l"(src))
#define CP_COMMIT() asm volatile("cp.async.commit_group;")
#define CP_WAIT0()  asm volatile("cp.async.wait_group 0;")

__device__ __forceinline__ unsigned sortable(float v) {
    unsigned u = __float_as_uint(v);
    return (u & 0x80000000u) ? ~u : (u | 0x80000000u);
}
__device__ __forceinline__ float unsortable(unsigned s) {
    unsigned u = (s & 0x80000000u) ? (s ^ 0x80000000u) : ~s;
    return __uint_as_float(u);
}

// ---------------------------------------------------------------------------
__global__ void kP(const float* __restrict__ yhat) {
    int b = blockIdx.x;
    int n = b >> 6, y = b & 63;
    int x = threadIdx.x;
    const float* p = yhat + (((long)n * CC) * HH + y) * WW + x;
    float s = 0.f;
    #pragma unroll 8
    for (int c = 0; c < CC; ++c) {
        float v = p[(long)c * HH * WW];
        s += v * v;
    }
    g_P[n][y][x] = s;
}

__global__ void kNorm() {
    int idx = blockIdx.x * blockDim.x + threadIdx.x;
    int n = idx >> 12, l = idx & 4095;
    int y = l >> 6, x = l & 63;
    float s = 0.f;
    #pragma unroll
    for (int o = 0; o < 4; ++o) {
        int yy = y + c_dy[o], xx = x + c_dx[o];
        if (yy >= 0 && xx >= 0 && xx < WW) s += g_P[n][yy][xx];
    }
    float nrm = fmaxf(sqrtf(s), 1e-12f);
    g_rnorm[n][l] = 1.0f / nrm;
    ((ull*)g_best)[idx] = 0ull;        // reset packed-best each replay
}

__global__ void kBuild(const float* __restrict__ yhat) {
    int e = blockIdx.x * blockDim.x + threadIdx.x;
    int l = e & 4095;
    int f = (e >> 12) & 255;
    int n = e >> 20;
    int y = l >> 6, x = l & 63;
    int off = f >> 6, c = f & 63;
    int yy = y + c_dy[off], xx = x + c_dx[off];
    float v = 0.f;
    if (yy >= 0 && xx >= 0 && xx < WW)
        v = yhat[(((long)n * CC + c) * HH + yy) * WW + xx];
    g_Ut[n][f][l] = v * g_rnorm[n][l];
}

// ---------------------------------------------------------------------------
// Triangular max-argmax GEMM.
// One 128x128 l-tile x 256-k per block. Double-buffered cp.async pipeline,
// k-chunks of 16. 8x8 microtile via f32x2 packed FMAs (register-side B dup).
// __launch_bounds__(256,3): target 3 CTAs/SM (84 regs) for latency hiding.
__global__ void __launch_bounds__(256, 3) kGemm() {
    // stage s: A [16][128] at s*4096, B [16][128] at s*4096 + 2048
    __shared__ __align__(16) float sm[8192];

    int n = blockIdx.y;
    int b = blockIdx.x;                 // 0..527: b = mt*(mt+1)/2 + lt
    int mt = (int)((sqrtf(8.f * b + 1.f) - 1.f) * 0.5f);
    while ((mt + 1) * (mt + 2) / 2 <= b) ++mt;
    while (mt * (mt + 1) / 2 > b) --mt;
    int lt = b - mt * (mt + 1) / 2;
    int m0 = mt << 7, l0 = lt << 7;

    const float* __restrict__ Ut = &g_Ut[n][0][0];

    int tid  = threadIdx.x;
    int w    = tid >> 5, lane = tid & 31;
    int tx   = ((w & 3) << 2) | (lane & 3);    // 0..15 (4 distinct per warp)
    int ty   = ((w >> 2) << 3) | (lane >> 2);  // 0..15 (8 distinct per warp)
    int row  = tid >> 4;                       // load row 0..15
    int c0   = tid & 15;                       // load float4 col base

    unsigned sbase = (unsigned)__cvta_generic_to_shared(sm);

    // prefetch chunk 0 into stage 0
    {
        const float* gr = Ut + (long)row * LL;
        #pragma unroll
        for (int q = 0; q < 2; ++q) {
            int c4 = c0 + (q << 4);
            CP16(sbase + ((row << 7) + (c4 << 2)) * 4, gr + l0 + (c4 << 2));
            CP16(sbase + (2048 + (row << 7) + (c4 << 2)) * 4, gr + m0 + (c4 << 2));
        }
        CP_COMMIT();
    }

    ull acc[4][8];
    #pragma unroll
    for (int i = 0; i < 4; ++i)
        #pragma unroll
        for (int j = 0; j < 8; ++j) acc[i][j] = 0ull;

    #pragma unroll 1
    for (int kc = 0; kc < 16; ++kc) {
        CP_WAIT0();
        __syncthreads();

        if (kc < 15) {                  // prefetch next chunk into other stage
            int k0 = (kc + 1) << 4;
            unsigned sdst = sbase + (((kc + 1) & 1) << 14);
            const float* gr = Ut + (long)(k0 + row) * LL;
            #pragma unroll
            for (int q = 0; q < 2; ++q) {
                int c4 = c0 + (q << 4);
                CP16(sdst + ((row << 7) + (c4 << 2)) * 4, gr + l0 + (c4 << 2));
                CP16(sdst + (2048 + (row << 7) + (c4 << 2)) * 4, gr + m0 + (c4 << 2));
            }
            CP_COMMIT();
        }

        const float* buf = sm + ((kc & 1) << 12);
        #pragma unroll
        for (int k = 0; k < 16; ++k) {
            const float* ra = buf + (k << 7);
            const float* rb = ra + 2048;
            ulonglong2 A0 = *(const ulonglong2*)(ra + (ty << 2));
            ulonglong2 A1 = *(const ulonglong2*)(ra + 64 + (ty << 2));
            float4 B0 = *(const float4*)(rb + (tx << 2));
            float4 B1 = *(const float4*)(rb + 64 + (tx << 2));
            ull ap[4] = {A0.x, A0.y, A1.x, A1.y};
            float bf[8] = {B0.x, B0.y, B0.z, B0.w, B1.x, B1.y, B1.z, B1.w};
            #pragma unroll
            for (int j = 0; j < 8; ++j) {
                ull bb;
                DUP2(bb, bf[j]);
                #pragma unroll
                for (int i = 0; i < 4; ++i) FMA2(acc[i][j], ap[i], bb);
            }
        }
    }

    // fold into per-thread best (causal l < m, first-occurrence ties)
    float bestv[8];
    int   bestl[8];
    #pragma unroll
    for (int j = 0; j < 8; ++j) { bestv[j] = -INFINITY; bestl[j] = 0x7fffffff; }

    #pragma unroll
    for (int j = 0; j < 8; ++j) {
        int m = m0 + ((j < 4) ? (tx << 2) + j : 64 + (tx << 2) + (j - 4));
        #pragma unroll
        for (int p = 0; p < 4; ++p) {
            int lb = l0 + ((p < 2) ? (ty << 2) + p * 2
                                   : 64 + (ty << 2) + (p - 2) * 2);
            ull a = acc[p][j];
            float v0 = __uint_as_float((unsigned)(a & 0xffffffffu));
            float v1 = __uint_as_float((unsigned)(a >> 32));
            if (lb < m && (v0 > bestv[j] || (v0 == bestv[j] && lb < bestl[j]))) {
                bestv[j] = v0; bestl[j] = lb;
            }
            int l1 = lb + 1;
            if (l1 < m && (v1 > bestv[j] || (v1 == bestv[j] && l1 < bestl[j]))) {
                bestv[j] = v1; bestl[j] = l1;
            }
        }
    }

    // cross-ty reduction in smem, then one packed atomicMax per m-column
    __syncthreads();
    float* rv = sm;                    // [128][16]
    int*   rl = (int*)(sm + 2048);     // [128][16]
    #pragma unroll
    for (int j = 0; j < 8; ++j) {
        int col = (j < 4) ? (tx << 2) + j : 64 + (tx << 2) + (j - 4);
        rv[col * 16 + ty] = bestv[j];
        rl[col * 16 + ty] = bestl[j];
    }
    __syncthreads();
    if (tid < 128) {
        float bv = rv[tid * 16];
        int   bl = rl[tid * 16];
        #pragma unroll
        for (int u = 1; u < 16; ++u) {
            float v = rv[tid * 16 + u];
            int   l = rl[tid * 16 + u];
            if (v > bv || (v == bv && l < bl)) { bv = v; bl = l; }
        }
        bv += 0.0f;                    // canonicalize -0.0 -> +0.0
        ull key = ((ull)sortable(bv) << 32) | (unsigned)(~bl);
        atomicMax(&g_best[n][m0 + tid], key);
    }
}

// ---------------------------------------------------------------------------
__global__ void kFinal(const float* __restrict__ yprob, float* __restrict__ out) {
    int idx = blockIdx.x * blockDim.x + threadIdx.x;   // n*LL + m
    int n = idx >> 12, m = idx & 4095;
    float S, U, A;
    int bl;
    if (m == 0) {
        S = 1e-8f; U = 1e-8f; A = -1.f; bl = -1;
    } else {
        ull key = g_best[n][m];
        float bv = unsortable((unsigned)(key >> 32));
        bl = (int)(~(unsigned)(key & 0xffffffffu));
        if (bv < 0.f) { bv = 0.f; bl = m; }
        S = fminf(fmaxf(bv, 1e-8f), 1.0f);
        U = fminf(fmaxf(yprob[n * LL + bl], 1e-8f), 1.0f);
        A = (float)bl;
    }
    g_arg[n][m] = bl;
    out[OUT_S + idx] = S;
    out[OUT_U + idx] = U;
    out[OUT_A + idx] = A;
}

__global__ void kOut(const float* __restrict__ yhat, float* __restrict__ out) {
    long e = (long)blockIdx.x * blockDim.x + threadIdx.x;
    int m = (int)(e & 4095);
    int t = (int)(e >> 12);
    int f = t % 576;
    int n = t / 576;
    float v = 0.f;
    if (m != 0) {
        int a  = g_arg[n][m];
        int c  = f / 9, ij = f % 9;
        int i  = ij / 3, j = ij % 3;
        int ay = a >> 6, ax = a & 63;
        int yy = ay + i - 1, xx = ax + j - 1;
        if (yy >= 0 && yy < HH && xx >= 0 && xx < WW)
            v = yhat[(((long)n * CC + c) * HH + yy) * WW + xx];
    }
    out[OUT_R + e] = v;
}

// ---------------------------------------------------------------------------
extern "C" void kernel_launch(void* const* d_in, const int* in_sizes, int n_in,
                              void* d_out, int out_size) {
    const float* yhat  = (const float*)d_in[0];
    const float* yprob = (const float*)d_in[1];
    float* out = (float*)d_out;

    kP<<<NB * HH, WW>>>(yhat);
    kNorm<<<(NB * LL) / 256, 256>>>();
    kBuild<<<(NB * FF * LL) / 256, 256>>>(yhat);
    kGemm<<<dim3(528, NB), 256>>>();
    kFinal<<<(NB * LL) / 256, 256>>>(yprob, out);
    kOut<<<(NB * 576 * LL) / 256, 256>>>(yhat, out);
}

// round 8
// speedup vs baseline: 1.2841x; 1.2841x over previous
#include <cuda_runtime.h>
#include <math.h>

#define NB 4
#define CC 64
#define HH 64
#define WW 64
#define LL 4096
#define FF 256

#define OUT_S 0
#define OUT_U 16384
#define OUT_R 32768
#define OUT_A 9469952

typedef unsigned long long ull;

__device__ float g_Ut[NB][FF][LL];     // normalized masked features, k-major
__device__ float g_P[NB][HH][WW];
__device__ float g_rnorm[NB][LL];
__device__ int   g_arg[NB][LL];
__device__ ull   g_best[NB][LL];       // packed (sortable(v)<<32) | ~l

__device__ __constant__ int c_dy[4] = {-1, -1, -1, 0};
__device__ __constant__ int c_dx[4] = {-1,  0,  1, -1};

// packed-f32x2 FMA: two fp32 FMAs per instruction, bit-identical per lane
#define FMA2(d, a, b) asm("fma.rn.f32x2 %0, %1, %2, %0;" : "+l"(d) : "l"(a), "l"(b))
#define DUP2(d, f)    asm("mov.b64 %0, {%1, %1};" : "=l"(d) : "r"(__float_as_uint(f)))

#define CP16(dst, src) asm volatile( \
    "cp.async.cg.shared.global [%0], [%1], 16;" :: "r"(dst), "l"(src))
#define CP_COMMIT() asm volatile("cp.async.commit_group;")
#define CP_WAIT1()  asm volatile("cp.async.wait_group 1;")

__device__ __forceinline__ unsigned sortable(float v) {
    unsigned u = __float_as_uint(v);
    return (u & 0x80000000u) ? ~u : (u | 0x80000000u);
}
__device__ __forceinline__ float unsortable(unsigned s) {
    unsigned u = (s & 0x80000000u) ? (s ^ 0x80000000u) : ~s;
    return __uint_as_float(u);
}

// ---------------------------------------------------------------------------
__global__ void kP(const float* __restrict__ yhat) {
    int b = blockIdx.x;
    int n = b >> 6, y = b & 63;
    int x = threadIdx.x;
    const float* p = yhat + (((long)n * CC) * HH + y) * WW + x;
    float s = 0.f;
    #pragma unroll 8
    for (int c = 0; c < CC; ++c) {
        float v = p[(long)c * HH * WW];
        s += v * v;
    }
    g_P[n][y][x] = s;
}

__global__ void kNorm() {
    int idx = blockIdx.x * blockDim.x + threadIdx.x;
    int n = idx >> 12, l = idx & 4095;
    int y = l >> 6, x = l & 63;
    float s = 0.f;
    #pragma unroll
    for (int o = 0; o < 4; ++o) {
        int yy = y + c_dy[o], xx = x + c_dx[o];
        if (yy >= 0 && xx >= 0 && xx < WW) s += g_P[n][yy][xx];
    }
    float nrm = fmaxf(sqrtf(s), 1e-12f);
    g_rnorm[n][l] = 1.0f / nrm;
    ((ull*)g_best)[idx] = 0ull;        // reset packed-best each replay
}

__global__ void kBuild(const float* __restrict__ yhat) {
    int e = blockIdx.x * blockDim.x + threadIdx.x;
    int l = e & 4095;
    int f = (e >> 12) & 255;
    int n = e >> 20;
    int y = l >> 6, x = l & 63;
    int off = f >> 6, c = f & 63;
    int yy = y + c_dy[off], xx = x + c_dx[off];
    float v = 0.f;
    if (yy >= 0 && xx >= 0 && xx < WW)
        v = yhat[(((long)n * CC + c) * HH + yy) * WW + xx];
    g_Ut[n][f][l] = v * g_rnorm[n][l];
}

// ---------------------------------------------------------------------------
// Triangular max-argmax GEMM.
// One 128x128 l-tile x 256-k per block. THREE-stage cp.async ring with
// prefetch distance 2 (wait_group 1; uniform empty commits keep the pending
// count invariant), k-chunks of 16. 8x8 microtile via f32x2 packed FMAs.
__global__ void __launch_bounds__(256) kGemm() {
    // stage s: A [16][128] at s*4096, B [16][128] at s*4096 + 2048
    __shared__ __align__(16) float sm[12288];

    int n = blockIdx.y;
    int b = blockIdx.x;                 // 0..527: b = mt*(mt+1)/2 + lt
    int mt = (int)((sqrtf(8.f * b + 1.f) - 1.f) * 0.5f);
    while ((mt + 1) * (mt + 2) / 2 <= b) ++mt;
    while (mt * (mt + 1) / 2 > b) --mt;
    int lt = b - mt * (mt + 1) / 2;
    int m0 = mt << 7, l0 = lt << 7;

    const float* __restrict__ Ut = &g_Ut[n][0][0];

    int tid  = threadIdx.x;
    int w    = tid >> 5, lane = tid & 31;
    int tx   = ((w & 3) << 2) | (lane & 3);    // 0..15 (4 distinct per warp)
    int ty   = ((w >> 2) << 3) | (lane >> 2);  // 0..15 (8 distinct per warp)
    int row  = tid >> 4;                       // load row 0..15
    int c0   = tid & 15;                       // load float4 col base

    unsigned sbase = (unsigned)__cvta_generic_to_shared(sm);

    // prefetch chunks 0 and 1 into stages 0 and 1
    #pragma unroll
    for (int pc = 0; pc < 2; ++pc) {
        const float* gr = Ut + (long)((pc << 4) + row) * LL;
        unsigned sdst = sbase + (pc << 14);    // pc*4096 floats *4B
        #pragma unroll
        for (int q = 0; q < 2; ++q) {
            int c4 = c0 + (q << 4);
            CP16(sdst + ((row << 7) + (c4 << 2)) * 4, gr + l0 + (c4 << 2));
            CP16(sdst + (2048 + (row << 7) + (c4 << 2)) * 4, gr + m0 + (c4 << 2));
        }
        CP_COMMIT();
    }

    ull acc[4][8];
    #pragma unroll
    for (int i = 0; i < 4; ++i)
        #pragma unroll
        for (int j = 0; j < 8; ++j) acc[i][j] = 0ull;

    int cs = 0;                         // compute stage
    int ps = 2;                         // prefetch stage (chunk kc+2)
    #pragma unroll 1
    for (int kc = 0; kc < 16; ++kc) {
        CP_WAIT1();                     // oldest pending (chunk kc) landed
        __syncthreads();

        if (kc < 14) {                  // prefetch chunk kc+2 into stage ps
            int k0 = (kc + 2) << 4;
            unsigned sdst = sbase + (ps << 14);
            const float* gr = Ut + (long)(k0 + row) * LL;
            #pragma unroll
            for (int q = 0; q < 2; ++q) {
                int c4 = c0 + (q << 4);
                CP16(sdst + ((row << 7) + (c4 << 2)) * 4, gr + l0 + (c4 << 2));
                CP16(sdst + (2048 + (row << 7) + (c4 << 2)) * 4, gr + m0 + (c4 << 2));
            }
        }
        CP_COMMIT();                    // uniform commit keeps pending count = 2

        const float* buf = sm + (cs << 12);
        #pragma unroll
        for (int k = 0; k < 16; ++k) {
            const float* ra = buf + (k << 7);
            const float* rb = ra + 2048;
            ulonglong2 A0 = *(const ulonglong2*)(ra + (ty << 2));
            ulonglong2 A1 = *(const ulonglong2*)(ra + 64 + (ty << 2));
            float4 B0 = *(const float4*)(rb + (tx << 2));
            float4 B1 = *(const float4*)(rb + 64 + (tx << 2));
            ull ap[4] = {A0.x, A0.y, A1.x, A1.y};
            float bf[8] = {B0.x, B0.y, B0.z, B0.w, B1.x, B1.y, B1.z, B1.w};
            #pragma unroll
            for (int j = 0; j < 8; ++j) {
                ull bb;
                DUP2(bb, bf[j]);
                #pragma unroll
                for (int i = 0; i < 4; ++i) FMA2(acc[i][j], ap[i], bb);
            }
        }
        cs = (cs == 2) ? 0 : cs + 1;
        ps = (ps == 2) ? 0 : ps + 1;
    }

    // fold into per-thread best (causal l < m, first-occurrence ties)
    float bestv[8];
    int   bestl[8];
    #pragma unroll
    for (int j = 0; j < 8; ++j) { bestv[j] = -INFINITY; bestl[j] = 0x7fffffff; }

    #pragma unroll
    for (int j = 0; j < 8; ++j) {
        int m = m0 + ((j < 4) ? (tx << 2) + j : 64 + (tx << 2) + (j - 4));
        #pragma unroll
        for (int p = 0; p < 4; ++p) {
            int lb = l0 + ((p < 2) ? (ty << 2) + p * 2
                                   : 64 + (ty << 2) + (p - 2) * 2);
            ull a = acc[p][j];
            float v0 = __uint_as_float((unsigned)(a & 0xffffffffu));
            float v1 = __uint_as_float((unsigned)(a >> 32));
            if (lb < m && (v0 > bestv[j] || (v0 == bestv[j] && lb < bestl[j]))) {
                bestv[j] = v0; bestl[j] = lb;
            }
            int l1 = lb + 1;
            if (l1 < m && (v1 > bestv[j] || (v1 == bestv[j] && l1 < bestl[j]))) {
                bestv[j] = v1; bestl[j] = l1;
            }
        }
    }

    // cross-ty reduction in smem, then one packed atomicMax per m-column
    __syncthreads();
    float* rv = sm;                    // [128][16]
    int*   rl = (int*)(sm + 2048);     // [128][16]
    #pragma unroll
    for (int j = 0; j < 8; ++j) {
        int col = (j < 4) ? (tx << 2) + j : 64 + (tx << 2) + (j - 4);
        rv[col * 16 + ty] = bestv[j];
        rl[col * 16 + ty] = bestl[j];
    }
    __syncthreads();
    if (tid < 128) {
        float bv = rv[tid * 16];
        int   bl = rl[tid * 16];
        #pragma unroll
        for (int u = 1; u < 16; ++u) {
            float v = rv[tid * 16 + u];
            int   l = rl[tid * 16 + u];
            if (v > bv || (v == bv && l < bl)) { bv = v; bl = l; }
        }
        bv += 0.0f;                    // canonicalize -0.0 -> +0.0
        ull key = ((ull)sortable(bv) << 32) | (unsigned)(~bl);
        atomicMax(&g_best[n][m0 + tid], key);
    }
}

// ---------------------------------------------------------------------------
__global__ void kFinal(const float* __restrict__ yprob, float* __restrict__ out) {
    int idx = blockIdx.x * blockDim.x + threadIdx.x;   // n*LL + m
    int n = idx >> 12, m = idx & 4095;
    float S, U, A;
    int bl;
    if (m == 0) {
        S = 1e-8f; U = 1e-8f; A = -1.f; bl = -1;
    } else {
        ull key = g_best[n][m];
        float bv = unsortable((unsigned)(key >> 32));
        bl = (int)(~(unsigned)(key & 0xffffffffu));
        if (bv < 0.f) { bv = 0.f; bl = m; }
        S = fminf(fmaxf(bv, 1e-8f), 1.0f);
        U = fminf(fmaxf(yprob[n * LL + bl], 1e-8f), 1.0f);
        A = (float)bl;
    }
    g_arg[n][m] = bl;
    out[OUT_S + idx] = S;
    out[OUT_U + idx] = U;
    out[OUT_A + idx] = A;
}

__global__ void kOut(const float* __restrict__ yhat, float* __restrict__ out) {
    long e = (long)blockIdx.x * blockDim.x + threadIdx.x;
    int m = (int)(e & 4095);
    int t = (int)(e >> 12);
    int f = t % 576;
    int n = t / 576;
    float v = 0.f;
    if (m != 0) {
        int a  = g_arg[n][m];
        int c  = f / 9, ij = f % 9;
        int i  = ij / 3, j = ij % 3;
        int ay = a >> 6, ax = a & 63;
        int yy = ay + i - 1, xx = ax + j - 1;
        if (yy >= 0 && yy < HH && xx >= 0 && xx < WW)
            v = yhat[(((long)n * CC + c) * HH + yy) * WW + xx];
    }
    out[OUT_R + e] = v;
}

// ---------------------------------------------------------------------------
extern "C" void kernel_launch(void* const* d_in, const int* in_sizes, int n_in,
                              void* d_out, int out_size) {
    const float* yhat  = (const float*)d_in[0];
    const float* yprob = (const float*)d_in[1];
    float* out = (float*)d_out;

    kP<<<NB * HH, WW>>>(yhat);
    kNorm<<<(NB * LL) / 256, 256>>>();
    kBuild<<<(NB * FF * LL) / 256, 256>>>(yhat);
    kGemm<<<dim3(528, NB), 256>>>();
    kFinal<<<(NB * LL) / 256, 256>>>(yprob, out);
    kOut<<<(NB * 576 * LL) / 256, 256>>>(yhat, out);
}

// round 11
// speedup vs baseline: 1.4139x; 1.1010x over previous
#include <cuda_runtime.h>
#include <cuda_bf16.h>
#include <math.h>
#include <stdint.h>

#define NB 4
#define LL 4096
#define FF 256

#define OUT_S 0
#define OUT_U 16384
#define OUT_R 32768
#define OUT_A 9469952

typedef unsigned long long ull;

__device__ float g_P[NB][64][64];
__device__ float g_rnorm[NB][LL];
__device__ __nv_bfloat16 g_Us[3][NB][LL][FF];   // bf16 splits, position-major
__device__ int   g_arg[NB][LL];
__device__ ull   g_best[NB][LL];

__constant__ int c_dy[4] = {-1, -1, -1, 0};
__constant__ int c_dx[4] = {-1,  0,  1, -1};

#define CP16(dst, src) asm volatile( \
    "cp.async.cg.shared.global [%0], [%1], 16;" :: "r"(dst), "l"(src))
#define CP_COMMIT() asm volatile("cp.async.commit_group;")
#define CP_WAIT0()  asm volatile("cp.async.wait_group 0;")

#define LDSM4(r0, r1, r2, r3, addr) \
    asm volatile("ldmatrix.sync.aligned.m8n8.x4.shared.b16 {%0,%1,%2,%3}, [%4];" \
                 : "=r"(r0), "=r"(r1), "=r"(r2), "=r"(r3) : "r"(addr))

#define MMA16816(c, a, b) \
    asm volatile("mma.sync.aligned.m16n8k16.row.col.f32.bf16.bf16.f32 " \
                 "{%0,%1,%2,%3}, {%4,%5,%6,%7}, {%8,%9}, {%0,%1,%2,%3};" \
                 : "+f"((c)[0]), "+f"((c)[1]), "+f"((c)[2]), "+f"((c)[3]) \
                 : "r"((a)[0]), "r"((a)[1]), "r"((a)[2]), "r"((a)[3]), \
                   "r"((b)[0]), "r"((b)[1]))

__device__ __forceinline__ unsigned sortable(float v) {
    unsigned u = __float_as_uint(v);
    return (u & 0x80000000u) ? ~u : (u | 0x80000000u);
}
__device__ __forceinline__ float unsortable(unsigned s) {
    unsigned u = (s & 0x80000000u) ? (s ^ 0x80000000u) : ~s;
    return __uint_as_float(u);
}

// ---------------------------------------------------------------------------
__global__ void kP(const float* __restrict__ yhat) {
    int b = blockIdx.x;
    int n = b >> 6, y = b & 63;
    int x = threadIdx.x;
    const float* p = yhat + (((long)n * 64) * 64 + y) * 64 + x;
    float s = 0.f;
    #pragma unroll 8
    for (int c = 0; c < 64; ++c) { float v = p[(long)c * 4096]; s += v * v; }
    g_P[n][y][x] = s;
}

__global__ void kNorm() {
    int idx = blockIdx.x * blockDim.x + threadIdx.x;
    int n = idx >> 12, l = idx & 4095;
    int y = l >> 6, x = l & 63;
    float s = 0.f;
    #pragma unroll
    for (int o = 0; o < 4; ++o) {
        int yy = y + c_dy[o], xx = x + c_dx[o];
        if (yy >= 0 && xx >= 0 && xx < 64) s += g_P[n][yy][xx];
    }
    g_rnorm[n][l] = 1.0f / fmaxf(sqrtf(s), 1e-12f);
    ((ull*)g_best)[idx] = 0ull;          // reset per replay
}

// Build bf16x3 splits of normalized features, position-major [n][l][f].
// Block = (n, patch-offset fb, y-row lb).
__global__ void __launch_bounds__(256) kSplit(const float* __restrict__ yhat) {
    __shared__ float sT[64][65];
    int b  = blockIdx.x;                  // n*256 + fb*64 + lb
    int lb = b & 63, fb = (b >> 6) & 3, n = b >> 8;
    int tid = threadIdx.x;
    int yy = lb + c_dy[fb];
    {   // phase 1: gather + normalize, x-coalesced
        int li = tid & 63, fi0 = tid >> 6;
        int l  = lb * 64 + li;
        float rn = g_rnorm[n][l];
        int xx = li + c_dx[fb];
        bool ok = (yy >= 0) && (xx >= 0) && (xx < 64);
        #pragma unroll
        for (int it = 0; it < 16; ++it) {
            int fi = fi0 + it * 4;
            float v = 0.f;
            if (ok) v = yhat[(((long)n * 64 + fi) * 64 + yy) * 64 + xx];
            sT[li][fi] = v * rn;
        }
    }
    __syncthreads();
    {   // phase 2: split + write rows (f contiguous)
        int lr = tid >> 2, fq = tid & 3;
        int pos = lb * 64 + lr;
        unsigned u1[8], u2[8], u3[8];
        #pragma unroll
        for (int k = 0; k < 16; ++k) {
            float v = sT[lr][fq * 16 + k];
            __nv_bfloat16 h1 = __float2bfloat16(v);
            float r1 = v - __bfloat162float(h1);
            __nv_bfloat16 h2 = __float2bfloat16(r1);
            float r2 = r1 - __bfloat162float(h2);
            __nv_bfloat16 h3 = __float2bfloat16(r2);
            unsigned b1 = __bfloat16_as_ushort(h1);
            unsigned b2 = __bfloat16_as_ushort(h2);
            unsigned b3 = __bfloat16_as_ushort(h3);
            int w = k >> 1, sh = (k & 1) * 16;
            if (sh == 0) { u1[w] = b1; u2[w] = b2; u3[w] = b3; }
            else { u1[w] |= b1 << 16; u2[w] |= b2 << 16; u3[w] |= b3 << 16; }
        }
        int f0 = fb * 64 + fq * 16;        // (fixed: include fb*64!)
        *(uint4*)&g_Us[0][n][pos][f0]     = *(uint4*)&u1[0];
        *(uint4*)&g_Us[0][n][pos][f0 + 8] = *(uint4*)&u1[4];
        *(uint4*)&g_Us[1][n][pos][f0]     = *(uint4*)&u2[0];
        *(uint4*)&g_Us[1][n][pos][f0 + 8] = *(uint4*)&u2[4];
        *(uint4*)&g_Us[2][n][pos][f0]     = *(uint4*)&u3[0];
        *(uint4*)&g_Us[2][n][pos][f0 + 8] = *(uint4*)&u3[4];
    }
}

// ---------------------------------------------------------------------------
// bf16x3 mma.sync GEMM. 128x128 tile per job, K=256 in chunks of 16.
// smem: 2 stages x 3 splits x (A[128][16] + B[128][16]) bf16, 48B rows.
#define ROWB   48u
#define SPLITB 6144u            // 128*48
#define STAGEB 36864u           // 6*6144

__global__ void __launch_bounds__(256, 2) kMMA() {
    extern __shared__ __align__(16) char dsm[];
    uint32_t sbase = (uint32_t)__cvta_generic_to_shared(dsm);

    int n = blockIdx.y;
    int b = blockIdx.x;                 // b = mt*(mt+1)/2 + lt
    int mt = (int)((sqrtf(8.f * b + 1.f) - 1.f) * 0.5f);
    while ((mt + 1) * (mt + 2) / 2 <= b) ++mt;
    while (mt * (mt + 1) / 2 > b) --mt;
    int lt = b - mt * (mt + 1) / 2;
    int m0 = mt << 7, l0 = lt << 7;
    bool diag = (lt == mt);
    uint32_t bOff = diag ? 0u : 18432u; // diag: B aliases A

    int tid  = threadIdx.x;
    int w    = tid >> 5, lane = tid & 31;
    int wm   = w & 1, wl = w >> 1;
    int g    = lane >> 2, tig = lane & 3;

    // cp.async task geometry: each thread owns one (row, 16B-half)
    int crow = tid >> 1, chalf = tid & 1;

    // LDSM lane offsets (within a split tile)
    uint32_t aoff[4], boff[2];
    #pragma unroll
    for (int im = 0; im < 4; ++im)
        aoff[im] = (uint32_t)((wm * 64 + im * 16 + (lane & 15)) * ROWB
                              + (lane >> 4) * 16);
    #pragma unroll
    for (int p = 0; p < 2; ++p)
        boff[p] = (uint32_t)((wl * 32 + p * 16 + (lane & 7) + ((lane >> 4) << 3)) * ROWB
                             + (((lane >> 3) & 1) << 4));

    // prefetch chunk 0
    {
        uint32_t st = sbase;
        #pragma unroll
        for (int tile = 0; tile < 6; ++tile) {
            if (tile >= 3 && diag) break;
            int sp = tile % 3; bool isB = tile >= 3;
            const __nv_bfloat16* src =
                &g_Us[sp][n][(isB ? l0 : m0) + crow][0] + (chalf << 3);
            CP16(st + (isB ? 18432u : 0u) + sp * SPLITB + crow * ROWB + (chalf << 4), src);
        }
        CP_COMMIT();
    }

    float acc[4][4][4];
    #pragma unroll
    for (int i = 0; i < 4; ++i)
        #pragma unroll
        for (int j = 0; j < 4; ++j)
            #pragma unroll
            for (int r = 0; r < 4; ++r) acc[i][j][r] = 0.f;

    unsigned af[4][4], bf[4][2];

    #pragma unroll 1
    for (int kc = 0; kc < 16; ++kc) {
        CP_WAIT0();
        __syncthreads();
        if (kc < 15) {                  // prefetch next chunk
            int k0 = (kc + 1) << 4;
            uint32_t st = sbase + (uint32_t)((kc + 1) & 1) * STAGEB;
            #pragma unroll
            for (int tile = 0; tile < 6; ++tile) {
                if (tile >= 3 && diag) break;
                int sp = tile % 3; bool isB = tile >= 3;
                const __nv_bfloat16* src =
                    &g_Us[sp][n][(isB ? l0 : m0) + crow][k0] + (chalf << 3);
                CP16(st + (isB ? 18432u : 0u) + sp * SPLITB + crow * ROWB + (chalf << 4), src);
            }
            CP_COMMIT();
        }

        uint32_t sA = sbase + (uint32_t)(kc & 1) * STAGEB;
        uint32_t sB = sA + bOff;

        #define LOADA(sp) do { \
            uint32_t base = sA + (sp) * SPLITB; \
            LDSM4(af[0][0], af[0][1], af[0][2], af[0][3], base + aoff[0]); \
            LDSM4(af[1][0], af[1][1], af[1][2], af[1][3], base + aoff[1]); \
            LDSM4(af[2][0], af[2][1], af[2][2], af[2][3], base + aoff[2]); \
            LDSM4(af[3][0], af[3][1], af[3][2], af[3][3], base + aoff[3]); \
        } while (0)
        #define LOADB(sp) do { \
            uint32_t base = sB + (sp) * SPLITB; \
            LDSM4(bf[0][0], bf[0][1], bf[1][0], bf[1][1], base + boff[0]); \
            LDSM4(bf[2][0], bf[2][1], bf[3][0], bf[3][1], base + boff[1]); \
        } while (0)
        #define PASS() do { \
            _Pragma("unroll") \
            for (int im = 0; im < 4; ++im) \
                _Pragma("unroll") \
                for (int in = 0; in < 4; ++in) \
                    MMA16816(acc[im][in], af[im], bf[in]); \
        } while (0)

        LOADA(0); LOADB(0); PASS();     // b1*b1
        LOADB(1); PASS();               // b1*b2
        LOADA(1); PASS();               // b2*b2
        LOADB(0); PASS();               // b2*b1
        LOADA(2); PASS();               // b3*b1
        LOADA(0); LOADB(2); PASS();     // b1*b3
    }

    // fold into per-thread best (causal l < m, explicit l tie-break)
    float bestv[8];
    int   bestl[8];
    #pragma unroll
    for (int s = 0; s < 8; ++s) { bestv[s] = -INFINITY; bestl[s] = 0x7fffffff; }

    #pragma unroll
    for (int im = 0; im < 4; ++im) {
        #pragma unroll
        for (int rh = 0; rh < 2; ++rh) {
            int s = im * 2 + rh;
            int m = m0 + wm * 64 + im * 16 + g + rh * 8;
            #pragma unroll
            for (int in = 0; in < 4; ++in) {
                #pragma unroll
                for (int cp = 0; cp < 2; ++cp) {
                    float v = acc[im][in][(rh << 1) | cp];
                    int l = l0 + wl * 32 + in * 8 + 2 * tig + cp;
                    if (l < m && (v > bestv[s] || (v == bestv[s] && l < bestl[s]))) {
                        bestv[s] = v; bestl[s] = l;
                    }
                }
            }
        }
    }

    // cross-thread reduction: m-row mm has 16 contributors (wl x tig)
    __syncthreads();
    float* rv = (float*)dsm;            // [128][16]
    int*   rl = (int*)(dsm + 8192);     // [128][16]
    #pragma unroll
    for (int im = 0; im < 4; ++im)
        #pragma unroll
        for (int rh = 0; rh < 2; ++rh) {
            int mm = wm * 64 + im * 16 + g + rh * 8;
            rv[mm * 16 + wl * 4 + tig] = bestv[im * 2 + rh];
            rl[mm * 16 + wl * 4 + tig] = bestl[im * 2 + rh];
        }
    __syncthreads();
    if (tid < 128) {
        float bv = rv[tid * 16];
        int   bl = rl[tid * 16];
        #pragma unroll
        for (int u = 1; u < 16; ++u) {
            float v = rv[tid * 16 + u];
            int   l = rl[tid * 16 + u];
            if (v > bv || (v == bv && l < bl)) { bv = v; bl = l; }
        }
        bv += 0.0f;                     // canonicalize -0.0
        ull key = ((ull)sortable(bv) << 32) | (unsigned)(~bl);
        atomicMax(&g_best[n][m0 + tid], key);
    }
}

// ---------------------------------------------------------------------------
__global__ void kFinal(const float* __restrict__ yprob, float* __restrict__ out) {
    int idx = blockIdx.x * blockDim.x + threadIdx.x;
    int n = idx >> 12, m = idx & 4095;
    float S, U, A;
    int bl;
    if (m == 0) {
        S = 1e-8f; U = 1e-8f; A = -1.f; bl = -1;
    } else {
        ull key = g_best[n][m];
        float bv = unsortable((unsigned)(key >> 32));
        bl = (int)(~(unsigned)(key & 0xffffffffu));
        if (bv < 0.f) { bv = 0.f; bl = m; }
        S = fminf(fmaxf(bv, 1e-8f), 1.0f);
        U = fminf(fmaxf(yprob[n * LL + bl], 1e-8f), 1.0f);
        A = (float)bl;
    }
    g_arg[n][m] = bl;
    out[OUT_S + idx] = S;
    out[OUT_U + idx] = U;
    out[OUT_A + idx] = A;
}

__global__ void kOut(const float* __restrict__ yhat, float* __restrict__ out) {
    long e = (long)blockIdx.x * blockDim.x + threadIdx.x;
    int m = (int)(e & 4095);
    int t = (int)(e >> 12);
    int f = t % 576;
    int n = t / 576;
    float v = 0.f;
    if (m != 0) {
        int a  = g_arg[n][m];
        int c  = f / 9, ij = f % 9;
        int i  = ij / 3, j = ij % 3;
        int ay = a >> 6, ax = a & 63;
        int yy = ay + i - 1, xx = ax + j - 1;
        if (yy >= 0 && yy < 64 && xx >= 0 && xx < 64)
            v = yhat[(((long)n * 64 + c) * 64 + yy) * 64 + xx];
    }
    out[OUT_R + e] = v;
}

// ---------------------------------------------------------------------------
extern "C" void kernel_launch(void* const* d_in, const int* in_sizes, int n_in,
                              void* d_out, int out_size) {
    const float* yhat  = (const float*)d_in[0];
    const float* yprob = (const float*)d_in[1];
    float* out = (float*)d_out;

    cudaFuncSetAttribute(kMMA, cudaFuncAttributeMaxDynamicSharedMemorySize,
                         2 * STAGEB);

    kP<<<NB * 64, 64>>>(yhat);
    kNorm<<<(NB * LL) / 256, 256>>>();
    kSplit<<<NB * 4 * 64, 256>>>(yhat);
    kMMA<<<dim3(528, NB), 256, 2 * STAGEB>>>();
    kFinal<<<(NB * LL) / 256, 256>>>(yprob, out);
    kOut<<<(NB * 576 * LL) / 256, 256>>>(yhat, out);
}

// round 12
// speedup vs baseline: 2.1227x; 1.5014x over previous
#include <cuda_runtime.h>
#include <cuda_fp16.h>
#include <math.h>
#include <stdint.h>

#define NB 4
#define LL 4096
#define FF 256

#define OUT_S 0
#define OUT_U 16384
#define OUT_R 32768
#define OUT_A 9469952

typedef unsigned long long ull;

__device__ float g_P[NB][64][64];
__device__ float g_rnorm[NB][LL];
__device__ __half g_Us[2][NB][LL][FF];   // fp16 splits, position-major
__device__ int   g_arg[NB][LL];
__device__ ull   g_best[NB][LL];

__constant__ int c_dy[4] = {-1, -1, -1, 0};
__constant__ int c_dx[4] = {-1,  0,  1, -1};

#define CP16(dst, src) asm volatile( \
    "cp.async.cg.shared.global [%0], [%1], 16;" :: "r"(dst), "l"(src))
#define CP_COMMIT() asm volatile("cp.async.commit_group;")
#define CP_WAIT0()  asm volatile("cp.async.wait_group 0;")

#define LDSM4(r0, r1, r2, r3, addr) \
    asm volatile("ldmatrix.sync.aligned.m8n8.x4.shared.b16 {%0,%1,%2,%3}, [%4];" \
                 : "=r"(r0), "=r"(r1), "=r"(r2), "=r"(r3) : "r"(addr))

#define MMA16816(c, a, b) \
    asm volatile("mma.sync.aligned.m16n8k16.row.col.f32.f16.f16.f32 " \
                 "{%0,%1,%2,%3}, {%4,%5,%6,%7}, {%8,%9}, {%0,%1,%2,%3};" \
                 : "+f"((c)[0]), "+f"((c)[1]), "+f"((c)[2]), "+f"((c)[3]) \
                 : "r"((a)[0]), "r"((a)[1]), "r"((a)[2]), "r"((a)[3]), \
                   "r"((b)[0]), "r"((b)[1]))

__device__ __forceinline__ unsigned sortable(float v) {
    unsigned u = __float_as_uint(v);
    return (u & 0x80000000u) ? ~u : (u | 0x80000000u);
}
__device__ __forceinline__ float unsortable(unsigned s) {
    unsigned u = (s & 0x80000000u) ? (s ^ 0x80000000u) : ~s;
    return __uint_as_float(u);
}

// ---------------------------------------------------------------------------
__global__ void kP(const float* __restrict__ yhat) {
    int b = blockIdx.x;
    int n = b >> 6, y = b & 63;
    int x = threadIdx.x;
    const float* p = yhat + (((long)n * 64) * 64 + y) * 64 + x;
    float s = 0.f;
    #pragma unroll 8
    for (int c = 0; c < 64; ++c) { float v = p[(long)c * 4096]; s += v * v; }
    g_P[n][y][x] = s;
}

__global__ void kNorm() {
    int idx = blockIdx.x * blockDim.x + threadIdx.x;
    int n = idx >> 12, l = idx & 4095;
    int y = l >> 6, x = l & 63;
    float s = 0.f;
    #pragma unroll
    for (int o = 0; o < 4; ++o) {
        int yy = y + c_dy[o], xx = x + c_dx[o];
        if (yy >= 0 && xx >= 0 && xx < 64) s += g_P[n][yy][xx];
    }
    g_rnorm[n][l] = 1.0f / fmaxf(sqrtf(s), 1e-12f);
    ((ull*)g_best)[idx] = 0ull;          // reset per replay
}

// Build fp16x2 splits of normalized features, position-major [n][l][f].
// Block = (n, patch-offset fb, y-row lb).
__global__ void __launch_bounds__(256) kSplit(const float* __restrict__ yhat) {
    __shared__ float sT[64][65];
    int b  = blockIdx.x;                  // n*256 + fb*64 + lb
    int lb = b & 63, fb = (b >> 6) & 3, n = b >> 8;
    int tid = threadIdx.x;
    int yy = lb + c_dy[fb];
    {   // phase 1: gather + normalize, x-coalesced
        int li = tid & 63, fi0 = tid >> 6;
        int l  = lb * 64 + li;
        float rn = g_rnorm[n][l];
        int xx = li + c_dx[fb];
        bool ok = (yy >= 0) && (xx >= 0) && (xx < 64);
        #pragma unroll
        for (int it = 0; it < 16; ++it) {
            int fi = fi0 + it * 4;
            float v = 0.f;
            if (ok) v = yhat[(((long)n * 64 + fi) * 64 + yy) * 64 + xx];
            sT[li][fi] = v * rn;
        }
    }
    __syncthreads();
    {   // phase 2: split + write rows (f contiguous)
        int lr = tid >> 2, fq = tid & 3;
        int pos = lb * 64 + lr;
        unsigned u1[8], u2[8];
        #pragma unroll
        for (int k = 0; k < 16; ++k) {
            float v = sT[lr][fq * 16 + k];
            __half h1 = __float2half(v);
            float r1 = v - __half2float(h1);
            __half h2 = __float2half(r1);
            unsigned b1 = __half_as_ushort(h1);
            unsigned b2 = __half_as_ushort(h2);
            int w = k >> 1, sh = (k & 1) * 16;
            if (sh == 0) { u1[w] = b1; u2[w] = b2; }
            else { u1[w] |= b1 << 16; u2[w] |= b2 << 16; }
        }
        int f0 = fb * 64 + fq * 16;
        *(uint4*)&g_Us[0][n][pos][f0]     = *(uint4*)&u1[0];
        *(uint4*)&g_Us[0][n][pos][f0 + 8] = *(uint4*)&u1[4];
        *(uint4*)&g_Us[1][n][pos][f0]     = *(uint4*)&u2[0];
        *(uint4*)&g_Us[1][n][pos][f0 + 8] = *(uint4*)&u2[4];
    }
}

// ---------------------------------------------------------------------------
// fp16x2 mma.sync GEMM. 128x128 tile per job, K=256 in chunks of 32
// (2 sub-chunks of 16 per barrier). 3 product passes: h2*h1, h1*h1, h1*h2.
// smem stage: 2 sub-chunks x {A-split0, A-split1, B-split0, B-split1}
//             each 128 rows x 16 cols fp16, 48B rows.
#define ROWB   48u
#define SPLITB 6144u             // 128*48
#define HALFB  24576u            // 4*SPLITB (one sub-chunk)
#define STAGEB 49152u            // 2 sub-chunks

__global__ void __launch_bounds__(256, 2) kMMA() {
    extern __shared__ __align__(16) char dsm[];
    uint32_t sbase = (uint32_t)__cvta_generic_to_shared(dsm);

    int n = blockIdx.y;
    int b = blockIdx.x;                 // b = mt*(mt+1)/2 + lt
    int mt = (int)((sqrtf(8.f * b + 1.f) - 1.f) * 0.5f);
    while ((mt + 1) * (mt + 2) / 2 <= b) ++mt;
    while (mt * (mt + 1) / 2 > b) --mt;
    int lt = b - mt * (mt + 1) / 2;
    int m0 = mt << 7, l0 = lt << 7;
    bool diag = (lt == mt);
    uint32_t bTile = diag ? 0u : 2u;    // diag: B aliases A tiles

    int tid  = threadIdx.x;
    int w    = tid >> 5, lane = tid & 31;
    int wm   = w & 1, wl = w >> 1;
    int g    = lane >> 2, tig = lane & 3;

    int crow = tid >> 1, chalf = tid & 1;   // cp.async task: (row, 16B half)

    uint32_t aoff[4], boff[2];
    #pragma unroll
    for (int im = 0; im < 4; ++im)
        aoff[im] = (uint32_t)((wm * 64 + im * 16 + (lane & 15)) * ROWB
                              + (lane >> 4) * 16);
    #pragma unroll
    for (int p = 0; p < 2; ++p)
        boff[p] = (uint32_t)((wl * 32 + p * 16 + (lane & 7) + ((lane >> 4) << 3)) * ROWB
                             + (((lane >> 3) & 1) << 4));

    // prefetch chunk 0 (both sub-chunks)
    {
        #pragma unroll
        for (int h = 0; h < 2; ++h) {
            #pragma unroll
            for (int tile = 0; tile < 4; ++tile) {
                if (tile >= 2 && diag) break;
                int sp = tile & 1; bool isB = tile >= 2;
                const __half* src =
                    &g_Us[sp][n][(isB ? l0 : m0) + crow][h * 16] + (chalf << 3);
                CP16(sbase + h * HALFB + tile * SPLITB + crow * ROWB + (chalf << 4), src);
            }
        }
        CP_COMMIT();
    }

    float acc[4][4][4];
    #pragma unroll
    for (int i = 0; i < 4; ++i)
        #pragma unroll
        for (int j = 0; j < 4; ++j)
            #pragma unroll
            for (int r = 0; r < 4; ++r) acc[i][j][r] = 0.f;

    unsigned af[4][4], bf[4][2];

    #pragma unroll 1
    for (int kc = 0; kc < 8; ++kc) {
        CP_WAIT0();
        __syncthreads();
        if (kc < 7) {                   // prefetch next 32-k chunk
            int k0 = (kc + 1) << 5;
            uint32_t st = sbase + (uint32_t)((kc + 1) & 1) * STAGEB;
            #pragma unroll
            for (int h = 0; h < 2; ++h) {
                #pragma unroll
                for (int tile = 0; tile < 4; ++tile) {
                    if (tile >= 2 && diag) break;
                    int sp = tile & 1; bool isB = tile >= 2;
                    const __half* src =
                        &g_Us[sp][n][(isB ? l0 : m0) + crow][k0 + h * 16] + (chalf << 3);
                    CP16(st + h * HALFB + tile * SPLITB + crow * ROWB + (chalf << 4), src);
                }
            }
            CP_COMMIT();
        }

        uint32_t stg = sbase + (uint32_t)(kc & 1) * STAGEB;

        #define LOADA(base) do { \
            LDSM4(af[0][0], af[0][1], af[0][2], af[0][3], (base) + aoff[0]); \
            LDSM4(af[1][0], af[1][1], af[1][2], af[1][3], (base) + aoff[1]); \
            LDSM4(af[2][0], af[2][1], af[2][2], af[2][3], (base) + aoff[2]); \
            LDSM4(af[3][0], af[3][1], af[3][2], af[3][3], (base) + aoff[3]); \
        } while (0)
        #define LOADB(base) do { \
            LDSM4(bf[0][0], bf[0][1], bf[1][0], bf[1][1], (base) + boff[0]); \
            LDSM4(bf[2][0], bf[2][1], bf[3][0], bf[3][1], (base) + boff[1]); \
        } while (0)
        #define PASS() do { \
            _Pragma("unroll") \
            for (int im = 0; im < 4; ++im) \
                _Pragma("unroll") \
                for (int in = 0; in < 4; ++in) \
                    MMA16816(acc[im][in], af[im], bf[in]); \
        } while (0)

        #pragma unroll
        for (int h = 0; h < 2; ++h) {
            uint32_t sA = stg + h * HALFB;
            uint32_t sB = sA + bTile * SPLITB;
            // order: h2*h1, h1*h1, h1*h2  (one operand reload per transition)
            LOADA(sA + SPLITB); LOADB(sB); PASS();
            LOADA(sA);                   PASS();
            LOADB(sB + SPLITB);          PASS();
        }
    }

    // fold into per-thread best (causal l < m, explicit l tie-break)
    float bestv[8];
    int   bestl[8];
    #pragma unroll
    for (int s = 0; s < 8; ++s) { bestv[s] = -INFINITY; bestl[s] = 0x7fffffff; }

    #pragma unroll
    for (int im = 0; im < 4; ++im) {
        #pragma unroll
        for (int rh = 0; rh < 2; ++rh) {
            int s = im * 2 + rh;
            int m = m0 + wm * 64 + im * 16 + g + rh * 8;
            #pragma unroll
            for (int in = 0; in < 4; ++in) {
                #pragma unroll
                for (int cp = 0; cp < 2; ++cp) {
                    float v = acc[im][in][(rh << 1) | cp];
                    int l = l0 + wl * 32 + in * 8 + 2 * tig + cp;
                    if (l < m && (v > bestv[s] || (v == bestv[s] && l < bestl[s]))) {
                        bestv[s] = v; bestl[s] = l;
                    }
                }
            }
        }
    }

    // cross-thread reduction: m-row has 16 contributors (wl x tig)
    __syncthreads();
    float* rv = (float*)dsm;            // [128][16]
    int*   rl = (int*)(dsm + 8192);     // [128][16]
    #pragma unroll
    for (int im = 0; im < 4; ++im)
        #pragma unroll
        for (int rh = 0; rh < 2; ++rh) {
            int mm = wm * 64 + im * 16 + g + rh * 8;
            rv[mm * 16 + wl * 4 + tig] = bestv[im * 2 + rh];
            rl[mm * 16 + wl * 4 + tig] = bestl[im * 2 + rh];
        }
    __syncthreads();
    if (tid < 128) {
        float bv = rv[tid * 16];
        int   bl = rl[tid * 16];
        #pragma unroll
        for (int u = 1; u < 16; ++u) {
            float v = rv[tid * 16 + u];
            int   l = rl[tid * 16 + u];
            if (v > bv || (v == bv && l < bl)) { bv = v; bl = l; }
        }
        bv += 0.0f;                     // canonicalize -0.0
        ull key = ((ull)sortable(bv) << 32) | (unsigned)(~bl);
        atomicMax(&g_best[n][m0 + tid], key);
    }
}

// ---------------------------------------------------------------------------
__global__ void kFinal(const float* __restrict__ yprob, float* __restrict__ out) {
    int idx = blockIdx.x * blockDim.x + threadIdx.x;
    int n = idx >> 12, m = idx & 4095;
    float S, U, A;
    int bl;
    if (m == 0) {
        S = 1e-8f; U = 1e-8f; A = -1.f; bl = -1;
    } else {
        ull key = g_best[n][m];
        float bv = unsortable((unsigned)(key >> 32));
        bl = (int)(~(unsigned)(key & 0xffffffffu));
        if (bv < 0.f) { bv = 0.f; bl = m; }
        S = fminf(fmaxf(bv, 1e-8f), 1.0f);
        U = fminf(fmaxf(yprob[n * LL + bl], 1e-8f), 1.0f);
        A = (float)bl;
    }
    g_arg[n][m] = bl;
    out[OUT_S + idx] = S;
    out[OUT_U + idx] = U;
    out[OUT_A + idx] = A;
}

__global__ void kOut(const float* __restrict__ yhat, float* __restrict__ out) {
    long e = (long)blockIdx.x * blockDim.x + threadIdx.x;
    int m = (int)(e & 4095);
    int t = (int)(e >> 12);
    int f = t % 576;
    int n = t / 576;
    float v = 0.f;
    if (m != 0) {
        int a  = g_arg[n][m];
        int c  = f / 9, ij = f % 9;
        int i  = ij / 3, j = ij % 3;
        int ay = a >> 6, ax = a & 63;
        int yy = ay + i - 1, xx = ax + j - 1;
        if (yy >= 0 && yy < 64 && xx >= 0 && xx < 64)
            v = yhat[(((long)n * 64 + c) * 64 + yy) * 64 + xx];
    }
    out[OUT_R + e] = v;
}

// ---------------------------------------------------------------------------
extern "C" void kernel_launch(void* const* d_in, const int* in_sizes, int n_in,
                              void* d_out, int out_size) {
    const float* yhat  = (const float*)d_in[0];
    const float* yprob = (const float*)d_in[1];
    float* out = (float*)d_out;

    cudaFuncSetAttribute(kMMA, cudaFuncAttributeMaxDynamicSharedMemorySize,
                         2 * STAGEB);

    kP<<<NB * 64, 64>>>(yhat);
    kNorm<<<(NB * LL) / 256, 256>>>();
    kSplit<<<NB * 4 * 64, 256>>>(yhat);
    kMMA<<<dim3(528, NB), 256, 2 * STAGEB>>>();
    kFinal<<<(NB * LL) / 256, 256>>>(yprob, out);
    kOut<<<(NB * 576 * LL) / 256, 256>>>(yhat, out);
}